// round 5
// baseline (speedup 1.0000x reference)
#include <cuda_runtime.h>
#include <cuda_bf16.h>
#include <math.h>

#define S   1024
#define B_  16
#define D_  768
#define H_  384
#define G3  1152   // 3*H
#define RNC 48     // CTAs per direction in recurrence
#define RJ  8      // h-columns per CTA (384/48)
#define RT  192    // threads per recurrence CTA

// ---------------- scratch (device globals; no allocation) ----------------
__device__ float         g_X [S*B_*D_];      // layer input,  (s*16+b, 768)
__device__ float         g_XG[2][S*B_*G3];   // gate proj, [dir][(s*16+b)*1152+g]
__device__ __nv_bfloat16 g_hbf[2][2][2][7680]; // [dir][phase][hi/lo][12 chunk][16 b][40]
__device__ unsigned      g_ctr[3][2];        // [layer][dir] barrier counters

// ---------------- patchify + counter reset ----------------
__global__ void patchify_k(const float* __restrict__ x) {
    unsigned gi = blockIdx.x * blockDim.x + threadIdx.x;
    if (gi < 6) ((unsigned*)g_ctr)[gi] = 0;
    unsigned j  = gi & 511;
    unsigned i  = (gi >> 9) & 511;
    unsigned bc = gi >> 18;
    unsigned c  = bc % 3;
    unsigned b  = bc / 3;
    unsigned s  = (i >> 4) * 32 + (j >> 4);
    unsigned k  = (((i & 15) << 4) + (j & 15)) * 3 + c;
    g_X[(size_t)(s * 16 + b) * 768 + k] = x[gi];
}

// ================= shared bf16 split helpers =================
#define SMBLK 5120          // halfs per GEMM buffer block (128 rows * 40)
#define ROWH  40            // padded row length in halfs (80 bytes)

__device__ __forceinline__ void split8(const float* v, uint4& H, uint4& L) {
    unsigned h[4], l[4];
#pragma unroll
    for (int i = 0; i < 4; i++) {
        float a = v[2*i], b = v[2*i+1];
        __nv_bfloat16 ha = __float2bfloat16_rn(a), hb = __float2bfloat16_rn(b);
        float ra = a - __bfloat162float(ha), rb = b - __bfloat162float(hb);
        __nv_bfloat16 la = __float2bfloat16_rn(ra), lb = __float2bfloat16_rn(rb);
        h[i] = (unsigned)__bfloat16_as_ushort(ha) | ((unsigned)__bfloat16_as_ushort(hb) << 16);
        l[i] = (unsigned)__bfloat16_as_ushort(la) | ((unsigned)__bfloat16_as_ushort(lb) << 16);
    }
    H = make_uint4(h[0], h[1], h[2], h[3]);
    L = make_uint4(l[0], l[1], l[2], l[3]);
}

#define LDSM4(r, addr) \
    asm volatile("ldmatrix.sync.aligned.m8n8.x4.shared.b16 {%0,%1,%2,%3},[%4];" \
        : "=r"((r)[0]), "=r"((r)[1]), "=r"((r)[2]), "=r"((r)[3]) : "r"(addr))

#define MMA16816(d, a, b) \
    asm volatile("mma.sync.aligned.m16n8k16.row.col.f32.bf16.bf16.f32 " \
        "{%0,%1,%2,%3},{%4,%5,%6,%7},{%8,%9},{%0,%1,%2,%3};" \
        : "+f"((d)[0]), "+f"((d)[1]), "+f"((d)[2]), "+f"((d)[3]) \
        : "r"((a)[0]), "r"((a)[1]), "r"((a)[2]), "r"((a)[3]), "r"((b)[0]), "r"((b)[1]))

// ================= bf16 split-3 tensor-core GEMM (unchanged) =================
__global__ void __launch_bounds__(256, 1) gemm_xg_k(const float* __restrict__ Wih,
                                                    const float* __restrict__ bih) {
    extern __shared__ __nv_bfloat16 SM[];
    int tid  = threadIdx.x;
    int lane = tid & 31;
    int w    = tid >> 5;
    int m0   = blockIdx.y * 128;
    int n0   = blockIdx.x * 128;
    int bm   = (w >> 1) * 32;
    int bn   = (w & 1) * 64;

    int r  = tid >> 1;
    int c0 = (tid & 1) * 16;
    const float* Ag = g_X + (size_t)(m0 + r) * 768 + c0;
    const float* Bg = Wih + (size_t)(n0 + r) * 768 + c0;

    unsigned sbase = (unsigned)__cvta_generic_to_shared(SM);
    unsigned a_off = (unsigned)((bm + (lane & 15)) * 80 + ((lane >> 4) & 1) * 16);
    unsigned b_off = (unsigned)((bn + ((lane >> 4) & 1) * 8 + (lane & 7)) * 80 + ((lane >> 3) & 1) * 16);

    float c[2][8][4];
#pragma unroll
    for (int i = 0; i < 2; i++)
#pragma unroll
        for (int j = 0; j < 8; j++)
#pragma unroll
            for (int q = 0; q < 4; q++) c[i][j][q] = 0.f;

    float av[16], bv[16];
#pragma unroll
    for (int i = 0; i < 4; i++) {
        *(float4*)(av + 4*i) = *(const float4*)(Ag + 4*i);
        *(float4*)(bv + 4*i) = *(const float4*)(Bg + 4*i);
    }

    for (int kc = 0; kc < 24; kc++) {
        int buf = kc & 1;
        __nv_bfloat16* base = SM + buf * 4 * SMBLK;
        {
            uint4 H0, L0, H1, L1;
            split8(av,     H0, L0);
            split8(av + 8, H1, L1);
            *(uint4*)(base + 0*SMBLK + r*ROWH + c0)     = H0;
            *(uint4*)(base + 0*SMBLK + r*ROWH + c0 + 8) = H1;
            *(uint4*)(base + 1*SMBLK + r*ROWH + c0)     = L0;
            *(uint4*)(base + 1*SMBLK + r*ROWH + c0 + 8) = L1;
            split8(bv,     H0, L0);
            split8(bv + 8, H1, L1);
            *(uint4*)(base + 2*SMBLK + r*ROWH + c0)     = H0;
            *(uint4*)(base + 2*SMBLK + r*ROWH + c0 + 8) = H1;
            *(uint4*)(base + 3*SMBLK + r*ROWH + c0)     = L0;
            *(uint4*)(base + 3*SMBLK + r*ROWH + c0 + 8) = L1;
        }
        if (kc < 23) {
            const float* An = Ag + (kc + 1) * 32;
            const float* Bn = Bg + (kc + 1) * 32;
#pragma unroll
            for (int i = 0; i < 4; i++) {
                *(float4*)(av + 4*i) = *(const float4*)(An + 4*i);
                *(float4*)(bv + 4*i) = *(const float4*)(Bn + 4*i);
            }
        }
        __syncthreads();

        unsigned bb = sbase + (unsigned)(buf * 4 * SMBLK * 2);
#pragma unroll
        for (int kk = 0; kk < 2; kk++) {
            unsigned ah[2][4], al[2][4], bh[4][4], bl[4][4];
#pragma unroll
            for (int mt = 0; mt < 2; mt++) {
                LDSM4(ah[mt], bb + 0*SMBLK*2 + a_off + mt*1280 + kk*32);
                LDSM4(al[mt], bb + 1*SMBLK*2 + a_off + mt*1280 + kk*32);
            }
#pragma unroll
            for (int np = 0; np < 4; np++) {
                LDSM4(bh[np], bb + 2*SMBLK*2 + b_off + np*1280 + kk*32);
                LDSM4(bl[np], bb + 3*SMBLK*2 + b_off + np*1280 + kk*32);
            }
#pragma unroll
            for (int mt = 0; mt < 2; mt++)
#pragma unroll
                for (int nt = 0; nt < 8; nt++) {
                    int np = nt >> 1, sel = (nt & 1) * 2;
                    MMA16816(c[mt][nt], ah[mt], &bh[np][sel]);
                    MMA16816(c[mt][nt], ah[mt], &bl[np][sel]);
                    MMA16816(c[mt][nt], al[mt], &bh[np][sel]);
                }
        }
        __syncthreads();
    }

#pragma unroll
    for (int mt = 0; mt < 2; mt++) {
        int m = m0 + bm + mt * 16 + (lane >> 2);
#pragma unroll
        for (int nt = 0; nt < 8; nt++) {
            int n = n0 + bn + nt * 8 + (lane & 3) * 2;
            int dir = n >= G3;
            int g = n - dir * G3;
            float b0v = bih[n], b1v = bih[n + 1];
            float* o = g_XG[dir];
            o[(size_t)m * G3 + g]           = c[mt][nt][0] + b0v;
            o[(size_t)m * G3 + g + 1]       = c[mt][nt][1] + b1v;
            o[(size_t)(m + 8) * G3 + g]     = c[mt][nt][2] + b0v;
            o[(size_t)(m + 8) * G3 + g + 1] = c[mt][nt][3] + b1v;
        }
    }
}

// ---------------- inter-CTA barrier (release arrive / acquire poll) ----------------
__device__ __forceinline__ void ctabar(unsigned* c, unsigned target) {
    __syncthreads();
    if (threadIdx.x == 0) {
        asm volatile("red.release.gpu.global.add.u32 [%0], 1;" :: "l"(c) : "memory");
        unsigned v;
        do {
            asm volatile("ld.acquire.gpu.global.u32 %0, [%1];" : "=r"(v) : "l"(c) : "memory");
        } while (v < target);
    }
    __syncthreads();
}

// ---------------- fast gate math ----------------
__device__ __forceinline__ float fsigmoid(float x) {
    return __fdividef(1.f, 1.f + __expf(-x));
}
__device__ __forceinline__ float ftanh_(float x) {
    return 1.f - __fdividef(2.f, __expf(2.f * x) + 1.f);   // exact at both tails
}

// ---------------- persistent bidirectional GRU layer (tensor-core matvec) ----------------
// 48 CTAs/dir, each owns 8 j-cols -> 24 gate rows = 3 n-tiles (r,z,n).
// Whh in SMEM bf16 hi/lo ldmatrix layout. h exchanged via global bf16 hi/lo planes.
// NEW: warp-owned h staging (no full-CTA sync before mma), xg prefetched across
// the barrier, fast gate math.
__global__ void __launch_bounds__(RT, 1) gru_layer_k(
    const float* __restrict__ Whh,   // [2][1152][384]
    const float* __restrict__ bhh,   // [2][1152]
    float* __restrict__ dout, int layer)
{
    extern __shared__ char smc[];
    __nv_bfloat16* Bs = (__nv_bfloat16*)smc;             // [2][12][32][40] = 61440 B
    __nv_bfloat16* As = (__nv_bfloat16*)(smc + 61440);   // [2][12][16][40] = 30720 B
    float*        red = (float*)(smc + 92160);           // [6][3][16][9]   = 10368 B

    int tid = threadIdx.x, lane = tid & 31, w = tid >> 5;
    int d   = blockIdx.x / RNC;
    int cid = blockIdx.x - d * RNC;
    int jb  = cid * RJ;
    unsigned* ctr = &g_ctr[layer][d];

    // ---- prologue: zero Bs, convert Whh slice to bf16 hi/lo ldmatrix layout ----
    for (int i = tid; i < 3840; i += RT) ((uint4*)Bs)[i] = make_uint4(0,0,0,0);
    __syncthreads();
    const float* W = Whh + (size_t)d * G3 * H_;
    for (int i = tid; i < 24 * H_; i += RT) {
        int n = i / H_;            // 0..23 : gate g = n>>3, jl = n&7
        int k = i - n * H_;
        int g = n >> 3, jl = n & 7;
        float v = W[(size_t)(g * H_ + jb + jl) * H_ + k];
        __nv_bfloat16 hi = __float2bfloat16_rn(v);
        __nv_bfloat16 lo = __float2bfloat16_rn(v - __bfloat162float(hi));
        int addr = (k >> 5) * 1280 + n * 40 + (k & 31);
        Bs[addr]         = hi;
        Bs[15360 + addr] = lo;
    }
    // zero phase-0 h planes (all CTAs write zeros; benign race)
    {
        uint4* z = (uint4*)g_hbf[d][0];
        for (int i = tid; i < 1920; i += RT) z[i] = make_uint4(0,0,0,0);
    }

    // gate-thread constants (tid<128: one (jl,b) output)
    int jl = tid >> 4, b = tid & 15;
    int j_g = jb + jl;
    float bhr = 0.f, bhz = 0.f, bhn = 0.f, hp = 0.f;
    float xr = 0.f, xz = 0.f, xn = 0.f;
    const float* xgbase = g_XG[d];
    if (tid < 128) {
        const float* bb = bhh + d * G3;
        bhr = bb[j_g]; bhz = bb[H_ + j_g]; bhn = bb[2 * H_ + j_g];
        // prefetch xg for step 0 (flies under the first barrier)
        int pos0 = d ? (S - 1) : 0;
        const float* xrow = xgbase + (size_t)(pos0 * B_ + b) * G3;
        xr = xrow[j_g]; xz = xrow[H_ + j_g]; xn = xrow[2 * H_ + j_g];
    }
    ctabar(ctr, RNC);

    unsigned sbase = (unsigned)__cvta_generic_to_shared(smc);
    unsigned Ab = sbase + 61440;
    unsigned Bb = sbase;
    unsigned a_off = (unsigned)((lane & 15) * 80 + ((lane >> 4) & 1) * 16);
    unsigned b_off = (unsigned)((((lane >> 4) & 1) * 8 + (lane & 7)) * 80 + ((lane >> 3) & 1) * 16);

    for (int t = 0; t < S; t++) {
        int pos = d ? (S - 1 - t) : t;

        // warp-owned h staging: warp w copies chunks 2w,2w+1 (both planes), 5120B
        {
            const uint4* src = (const uint4*)g_hbf[d][t & 1];
            uint4* dst = (uint4*)As;
#pragma unroll
            for (int q = 0; q < 10; q++) {
                int e  = q * 32 + lane;          // 0..319 over this warp's region
                int p  = (e >= 160);
                int e2 = e - p * 160;
                int cc = (e2 >= 80);
                int off = e2 - cc * 80;
                int ui = p * 960 + (2 * w + cc) * 80 + off;   // uint4 index in As
                dst[ui] = src[ui];
            }
        }
        __syncwarp();

        // tensor-core matvec: warp w handles k-chunks 2w, 2w+1 (64 k each)
        float acc[3][4];
#pragma unroll
        for (int nt = 0; nt < 3; nt++)
#pragma unroll
            for (int q = 0; q < 4; q++) acc[nt][q] = 0.f;

#pragma unroll
        for (int cc = 0; cc < 2; cc++) {
            int ck = 2 * w + cc;
#pragma unroll
            for (int kk = 0; kk < 2; kk++) {
                unsigned ah[4], al[4], bh0[4], bh1[4], bl0[4], bl1[4];
                unsigned ab = Ab + ck * 1280 + a_off + kk * 32;
                LDSM4(ah, ab);
                LDSM4(al, ab + 15360);
                unsigned bb2 = Bb + ck * 2560 + b_off + kk * 32;
                LDSM4(bh0, bb2);
                LDSM4(bh1, bb2 + 1280);
                LDSM4(bl0, bb2 + 30720);
                LDSM4(bl1, bb2 + 30720 + 1280);
                MMA16816(acc[0], ah, &bh0[0]); MMA16816(acc[0], ah, &bl0[0]); MMA16816(acc[0], al, &bh0[0]);
                MMA16816(acc[1], ah, &bh0[2]); MMA16816(acc[1], ah, &bl0[2]); MMA16816(acc[1], al, &bh0[2]);
                MMA16816(acc[2], ah, &bh1[0]); MMA16816(acc[2], ah, &bl1[0]); MMA16816(acc[2], al, &bh1[0]);
            }
        }
        // dump partials: red[w][nt][row(b)][col(j), pad 9]
        {
            int row = lane >> 2, colb = (lane & 3) * 2;
#pragma unroll
            for (int nt = 0; nt < 3; nt++) {
                float* rb = red + ((w * 3 + nt) * 16 + row) * 9 + colb;
                rb[0]  = acc[nt][0];
                rb[1]  = acc[nt][1];
                rb[72] = acc[nt][2];
                rb[73] = acc[nt][3];
            }
        }
        __syncthreads();

        // gate math + state update (128 threads)
        if (tid < 128) {
            float sr = bhr, sz = bhz, sn = bhn;
#pragma unroll
            for (int ww = 0; ww < 6; ww++) {
                sr += red[((ww * 3 + 0) * 16 + b) * 9 + jl];
                sz += red[((ww * 3 + 1) * 16 + b) * 9 + jl];
                sn += red[((ww * 3 + 2) * 16 + b) * 9 + jl];
            }
            float rg = fsigmoid(xr + sr);
            float zg = fsigmoid(xz + sz);
            float ng = ftanh_(xn + rg * sn);
            float hv = (1.f - zg) * ng + zg * hp;
            hp = hv;
            // write bf16 hi/lo planes for next phase (A-fragment layout)
            __nv_bfloat16 hi = __float2bfloat16_rn(hv);
            __nv_bfloat16 lo = __float2bfloat16_rn(hv - __bfloat162float(hi));
            int haddr = (j_g >> 5) * 640 + b * 40 + (j_g & 31);
            g_hbf[d][(t + 1) & 1][0][haddr] = hi;
            g_hbf[d][(t + 1) & 1][1][haddr] = lo;
            if (layer == 2)
                dout[((size_t)(b * S + pos)) * D_ + d * H_ + j_g] = hv;
            else
                g_X[((size_t)(pos * B_ + b)) * D_ + d * H_ + j_g] = hv;
            // prefetch xg for step t+1 (flies under the barrier)
            int tn = t + 1;
            if (tn < S) {
                int posn = d ? (S - 1 - tn) : tn;
                const float* xrow = xgbase + (size_t)(posn * B_ + b) * G3;
                xr = xrow[j_g]; xz = xrow[H_ + j_g]; xn = xrow[2 * H_ + j_g];
            }
        }

        if (t < S - 1) ctabar(ctr, (unsigned)RNC * (t + 2));
    }
}

// ---------------- launch ----------------
extern "C" void kernel_launch(void* const* d_in, const int* in_sizes, int n_in,
                              void* d_out, int out_size) {
    const float* x    = (const float*)d_in[0];
    const float* W_ih = (const float*)d_in[1];
    const float* W_hh = (const float*)d_in[2];
    const float* b_ih = (const float*)d_in[3];
    const float* b_hh = (const float*)d_in[4];
    float* out = (float*)d_out;

    int gsm = 61440 + 30720 + 10368;                  // 102,528 B
    cudaFuncSetAttribute(gru_layer_k, cudaFuncAttributeMaxDynamicSharedMemorySize, gsm);
    int msm = 2 * 4 * SMBLK * 2;                      // 81,920 B
    cudaFuncSetAttribute(gemm_xg_k, cudaFuncAttributeMaxDynamicSharedMemorySize, msm);

    patchify_k<<<49152, 256>>>(x);
    for (int l = 0; l < 3; l++) {
        dim3 gg(2304 / 128, 16384 / 128);   // (18,128)
        gemm_xg_k<<<gg, 256, msm>>>(W_ih + (size_t)l * 2 * G3 * D_,
                                    b_ih + (size_t)l * 2 * G3);
        gru_layer_k<<<2 * RNC, RT, gsm>>>(W_hh + (size_t)l * 2 * G3 * H_,
                                          b_hh + (size_t)l * 2 * G3,
                                          out, l);
    }
}